// round 5
// baseline (speedup 1.0000x reference)
#include <cuda_runtime.h>
#include <math.h>

#define E 64
#define CHUNK 64                  // tokens per routing chunk
#define MAX_TOK 16384
#define MAX_CHUNKS (MAX_TOK / CHUNK)

// Scratch (no allocations allowed)
__device__ int   g_idx[MAX_TOK];      // per-token argmax expert
__device__ float g_gate[MAX_TOK];     // per-token softmax prob at argmax
__device__ int   g_hist[MAX_CHUNKS * E];

// ---------------------------------------------------------------------------
// Kernel 1: fill + embedded routing.
// Every block zero-streams one token's rows in BOTH output tensors.
// Blocks b < nchunks additionally compute routing for chunk b first
// (64 tokens x 4 threads = 256 threads); that work hides under the
// DRAM-saturated fill done by the other ~8k blocks.
// ---------------------------------------------------------------------------
__global__ void fill_route_kernel(const float* __restrict__ in,
                                  float* __restrict__ out,
                                  size_t sec, int row, int s, int nchunks,
                                  int write_mask) {
    __shared__ int hist[E];

    int b   = blockIdx.x;
    int tid = threadIdx.x;            // 0..255

    // ---- routing phase (first nchunks blocks only) ----
    if (b < nchunks) {
        if (tid < E) hist[tid] = 0;

        int t_local = tid >> 2;       // token within chunk 0..63
        int part    = tid & 3;        // 16-expert slice
        int token   = b * CHUNK + t_local;
        bool valid  = (token < s);
        int  tok_c  = valid ? token : (s - 1);

        const float4* p4 = (const float4*)(in + (size_t)tok_c * E + part * 16);
        float4 va = p4[0], vb = p4[1], vc = p4[2], vd = p4[3];
        float v[16] = {va.x, va.y, va.z, va.w, vb.x, vb.y, vb.z, vb.w,
                       vc.x, vc.y, vc.z, vc.w, vd.x, vd.y, vd.z, vd.w};

        float m = v[0];
        int   am = part * 16;
#pragma unroll
        for (int k = 1; k < 16; k++)
            if (v[k] > m) { m = v[k]; am = part * 16 + k; }
#pragma unroll
        for (int off = 1; off < 4; off <<= 1) {
            float mo = __shfl_xor_sync(0xffffffffu, m, off);
            int   ao = __shfl_xor_sync(0xffffffffu, am, off);
            if (mo > m || (mo == m && ao < am)) { m = mo; am = ao; }
        }
        float sum = 0.f;
#pragma unroll
        for (int k = 0; k < 16; k++) sum += __expf(v[k] - m);
#pragma unroll
        for (int off = 1; off < 4; off <<= 1)
            sum += __shfl_xor_sync(0xffffffffu, sum, off);

        __syncthreads();              // hist zeroed
        if (valid && part == 0) {
            g_idx[token]  = am;
            g_gate[token] = 1.0f / sum;
            atomicAdd(&hist[am], 1);
        }
        __syncthreads();
        if (tid < E) g_hist[b * E + tid] = hist[tid];
    }

    // ---- fill phase (all blocks): zero this token's rows ----
    int n4 = row >> 2;
    float4* __restrict__ c4 = (float4*)(out + (size_t)b * row);
    float4* __restrict__ m4 = (float4*)(out + sec + (size_t)b * row);
    float4 z = make_float4(0.f, 0.f, 0.f, 0.f);

    if (write_mask) {
        for (int i = tid; i < n4; i += blockDim.x) {
            __stcs(&c4[i], z);
            __stcs(&m4[i], z);
        }
    } else {
        for (int i = tid; i < n4; i += blockDim.x)
            __stcs(&c4[i], z);
    }
}

// ---------------------------------------------------------------------------
// Kernel 2: fused cross-chunk prefix + in-chunk rank + direct scatter.
// grid = nchunks, 64 threads (thread t = token t of chunk).
// Rank within chunk = warp match_any + warp0 per-expert count carried to
// warp1 via smem. Scatter writes land on memory zeroed by kernel 1
// (ordered by kernel boundary).
// ---------------------------------------------------------------------------
__global__ void slot_scatter_kernel(float* __restrict__ out, size_t sec,
                                    int row, int s, int cap, int write_mask) {
    extern __shared__ int hist_sh[];          // blk * E ints (preceding chunks)
    __shared__ int base_sh[E];
    __shared__ int idx_sh[CHUNK];
    __shared__ int w0cnt[E];

    int blk = blockIdx.x;
    int tid = threadIdx.x;                    // 0..63

    int need = blk * E;
    for (int i = tid; i < need; i += 64) hist_sh[i] = g_hist[i];
    if (tid < E) w0cnt[tid] = 0;

    int base = blk * CHUNK;
    int tokens = s - base;
    if (tokens > CHUNK) tokens = CHUNK;
    if (tid < tokens) idx_sh[tid] = g_idx[base + tid];
    __syncthreads();

    if (tid < E) {
        int r = 0;
        for (int c = 0; c < blk; c++) r += hist_sh[c * E + tid];
        base_sh[tid] = r;
    }
    __syncthreads();

    int e = (tid < tokens) ? idx_sh[tid] : -1;
    unsigned mask = __match_any_sync(0xffffffffu, e);
    int lane   = tid & 31;
    int within = __popc(mask & ((1u << lane) - 1));
    if (tid < 32 && within == 0 && e >= 0) w0cnt[e] = __popc(mask);
    __syncthreads();

    if (tid < tokens && e >= 0) {
        int r = base_sh[e] + within + ((tid >= 32) ? w0cnt[e] : 0);
        if (r < cap) {
            size_t off = (size_t)(base + tid) * row + e * cap + r;
            out[off] = g_gate[base + tid];
            if (write_mask) out[sec + off] = 1.0f;
        }
    }
}

// ---------------------------------------------------------------------------
// Kernel 3: zero any tail beyond the two tensors (output poisoned 0xAA)
// ---------------------------------------------------------------------------
__global__ void tail_zero(float* __restrict__ out, size_t start, size_t end) {
    size_t i = start + blockIdx.x * (size_t)blockDim.x + threadIdx.x;
    size_t stride = gridDim.x * (size_t)blockDim.x;
    for (; i < end; i += stride) out[i] = 0.f;
}

// ---------------------------------------------------------------------------
extern "C" void kernel_launch(void* const* d_in, const int* in_sizes, int n_in,
                              void* d_out, int out_size) {
    const float* in = (const float*)d_in[0];
    float* out = (float*)d_out;

    int total = in_sizes[0];
    int s = total / E;
    int cap = (int)floor(1.25 * (double)s / (double)E);
    cap += (cap & 1);
    if (cap < 4) cap = 4;

    int row = E * cap;
    size_t sec = (size_t)s * (size_t)row;
    int write_mask = ((size_t)out_size >= 2 * sec) ? 1 : 0;

    int nchunks = (s + CHUNK - 1) / CHUNK;

    // 1) fill (all tokens) + embedded routing (first nchunks blocks)
    fill_route_kernel<<<s, 256>>>(in, out, sec, row, s, nchunks, write_mask);

    // 2) prefix + rank + scatter (dyn smem = preceding-chunk hist table)
    size_t smem_bytes = (size_t)nchunks * E * sizeof(int);  // <= 32 KB
    slot_scatter_kernel<<<nchunks, 64, smem_bytes>>>(out, sec, row, s, cap,
                                                     write_mask);

    // 3) tail beyond 2*sec, if any
    size_t covered = write_mask ? 2 * sec : sec;
    if ((size_t)out_size > covered) {
        tail_zero<<<256, 256>>>(out, covered, (size_t)out_size);
    }
}